// round 16
// baseline (speedup 1.0000x reference)
#include <cuda_runtime.h>
#include <math.h>

// Shape (fixed): B=16, L=512, H=8, D=64, k = int(log 512) = 6
// Identity: sum_t irfft(conj(Q)*K)[t] = (sum_d q)(sum_d k), so
// x_corr_mean[b,l] = (1/(H*L)) * sum_h (sum_d q[b,l,h,:]) (sum_d k[b,l,h,:]).
//
// Fused kernel (single launch):
//   1024 blocks x 256 threads; warp w computes row blockIdx.x*8+w.
//   One acq_rel atomic per block on a PADDED per-batch counter (one counter
//   per 128B line -> independent LTS partitions; 64-deep same-address chain
//   ~0.5us). The 64th arriver's warp 0 runs top-6 + softmax + gather.
//   Phase 2 uses a STREAMING per-lane top-6 (12 regs) instead of holding all
//   512 scores in registers, so phase-1 occupancy is not deflated.
//   Counters monotonic (64 | 2^32) -> graph-replay safe.

#define B_ 16
#define L_ 512
#define H_ 8
#define HD_ 512
#define K_TOP 6
#define ROWS_PER_BLK 8
#define BLKS_PER_BATCH 64   // 512 / 8
#define CNT_STRIDE 32       // one u32 counter per 128B line

__device__ float g_scores[B_ * L_];
__device__ unsigned int g_cnt[B_ * CNT_STRIDE];  // never reset

// Order-preserving (score,index) pack: bigger score wins, ties -> lower index.
__device__ __forceinline__ unsigned long long packKI(float v, int idx) {
    unsigned int b = __float_as_uint(v);
    b = (b & 0x80000000u) ? ~b : (b | 0x80000000u);
    return ((unsigned long long)b << 32) | (unsigned int)(L_ - 1 - idx);
}
__device__ __forceinline__ float unpackV(unsigned long long p) {
    unsigned int u = (unsigned int)(p >> 32);
    u = (u & 0x80000000u) ? (u ^ 0x80000000u) : ~u;
    return __uint_as_float(u);
}
__device__ __forceinline__ int unpackI(unsigned long long p) {
    return L_ - 1 - (int)(p & 0xFFFFFFFFu);
}
__device__ __forceinline__ unsigned long long u64max(unsigned long long a,
                                                    unsigned long long b) {
    return a > b ? a : b;
}
__device__ __forceinline__ unsigned long long u64min(unsigned long long a,
                                                    unsigned long long b) {
    return a < b ? a : b;
}

// Branch-free insertion of v into descending best[6].
__device__ __forceinline__ void ins6(unsigned long long* best,
                                     unsigned long long v) {
    #pragma unroll
    for (int j = 0; j < K_TOP; j++) {
        unsigned long long lo = u64min(best[j], v);
        best[j] = u64max(best[j], v);
        v = lo;
    }
}

__global__ __launch_bounds__(256, 7) void fused_kernel(
    const float* __restrict__ q, const float* __restrict__ k,
    const float* __restrict__ values, float* __restrict__ out)
{
    const int lane = threadIdx.x & 31;
    const int w    = threadIdx.x >> 5;                 // warp 0..7
    const int bl   = blockIdx.x * ROWS_PER_BLK + w;    // row 0..8191
    const int b    = blockIdx.x >> 6;                  // batch

    // ---- Phase 1: one warp per row (proven numerics) ----------------------
    const float4* qp = reinterpret_cast<const float4*>(q) + (size_t)bl * 128;
    const float4* kp = reinterpret_cast<const float4*>(k) + (size_t)bl * 128;

    float qs[4], ks[4];
    #pragma unroll
    for (int j = 0; j < 4; j++) {
        float4 q4 = __ldg(qp + lane + 32 * j);
        float4 k4 = __ldg(kp + lane + 32 * j);
        qs[j] = q4.x + q4.y + q4.z + q4.w;
        ks[j] = k4.x + k4.y + k4.z + k4.w;
    }
    #pragma unroll
    for (int o = 8; o > 0; o >>= 1) {
        #pragma unroll
        for (int j = 0; j < 4; j++) {
            qs[j] += __shfl_down_sync(0xFFFFFFFFu, qs[j], o);
            ks[j] += __shfl_down_sync(0xFFFFFFFFu, ks[j], o);
        }
    }
    float p = qs[0] * ks[0] + qs[1] * ks[1] + qs[2] * ks[2] + qs[3] * ks[3];
    p += __shfl_down_sync(0xFFFFFFFFu, p, 16);
    if (lane == 0)
        g_scores[bl] = p * (1.0f / (H_ * L_));

    __syncthreads();            // orders all 8 score stores before the RMW
    if (w != 0) return;         // warps 1..7 done

    int win = 0;
    if (lane == 0) {
        unsigned int old;
        asm volatile("atom.acq_rel.gpu.global.add.u32 %0, [%1], %2;"
                     : "=r"(old)
                     : "l"(g_cnt + (size_t)b * CNT_STRIDE), "r"(1u)
                     : "memory");
        win = ((old & (unsigned)(BLKS_PER_BATCH - 1)) ==
               (unsigned)(BLKS_PER_BATCH - 1));
    }
    win = __shfl_sync(0xFFFFFFFFu, win, 0);
    if (!win) return;

    // ---- Phase 2 (winner block's warp 0): top-6 + softmax + gather --------
    // Streaming per-lane top-6 over this lane's 16 scores (low reg pressure).
    unsigned long long best[K_TOP] = {0ull, 0ull, 0ull, 0ull, 0ull, 0ull};
    const float4* sp = reinterpret_cast<const float4*>(g_scores + b * L_);
    #pragma unroll
    for (int v4i = 0; v4i < 4; v4i++) {
        float4 s4 = __ldcg(sp + lane * 4 + v4i);
        int base = lane * 16 + v4i * 4;
        ins6(best, packKI(s4.x, base + 0));
        ins6(best, packKI(s4.y, base + 1));
        ins6(best, packKI(s4.z, base + 2));
        ins6(best, packKI(s4.w, base + 3));
    }

    // Merge the 32 sorted lists: 6 rounds of warp-max over each lane's head.
    unsigned long long top[K_TOP];
    #pragma unroll
    for (int r = 0; r < K_TOP; r++) {
        unsigned long long m = best[0];
        #pragma unroll
        for (int o = 16; o > 0; o >>= 1)
            m = u64max(m, __shfl_xor_sync(0xFFFFFFFFu, m, o));
        top[r] = m;
        if (best[0] == m) {     // unique owner lane pops its head
            #pragma unroll
            for (int j = 0; j < K_TOP - 1; j++) best[j] = best[j + 1];
            best[K_TOP - 1] = 0ull;
        }
    }

    // Softmax (top[0] is the max) — redundant per lane, no broadcast.
    float m0 = unpackV(top[0]);
    float wgt[K_TOP];
    float s = 0.0f;
    #pragma unroll
    for (int i = 0; i < K_TOP; i++) { wgt[i] = __expf(unpackV(top[i]) - m0); s += wgt[i]; }
    float inv = 1.0f / s;

    // out[b,:] = sum_i w[i] * V[b, idx_i, :]  (128 float4, 4 per lane).
    const float4* vb = reinterpret_cast<const float4*>(values) + (size_t)b * L_ * 128;
    float4 acc[4];
    #pragma unroll
    for (int j = 0; j < 4; j++) acc[j] = make_float4(0.f, 0.f, 0.f, 0.f);

    #pragma unroll
    for (int i = 0; i < K_TOP; i++) {
        float wi = wgt[i] * inv;
        const float4* vp = vb + (size_t)unpackI(top[i]) * 128 + lane;
        #pragma unroll
        for (int j = 0; j < 4; j++) {
            float4 v4 = __ldg(vp + 32 * j);
            acc[j].x = fmaf(wi, v4.x, acc[j].x);
            acc[j].y = fmaf(wi, v4.y, acc[j].y);
            acc[j].z = fmaf(wi, v4.z, acc[j].z);
            acc[j].w = fmaf(wi, v4.w, acc[j].w);
        }
    }
    float4* op = reinterpret_cast<float4*>(out) + (size_t)b * 128 + lane;
    #pragma unroll
    for (int j = 0; j < 4; j++) op[32 * j] = acc[j];
}

extern "C" void kernel_launch(void* const* d_in, const int* in_sizes, int n_in,
                              void* d_out, int out_size)
{
    const float* q = (const float*)d_in[0];
    const float* k = (const float*)d_in[1];
    const float* v = (const float*)d_in[2];
    float* out = (float*)d_out;

    fused_kernel<<<(B_ * L_) / ROWS_PER_BLK, 256>>>(q, k, v, out);
}

// round 17
// speedup vs baseline: 1.0329x; 1.0329x over previous
#include <cuda_runtime.h>
#include <math.h>

// Shape (fixed): B=16, L=512, H=8, D=64, k = int(log 512) = 6
// Identity: sum_t irfft(conj(Q)*K)[t] = (sum_d q)(sum_d k), so
// x_corr_mean[b,l] = (1/(H*L)) * sum_h (sum_d q[b,l,h,:]) (sum_d k[b,l,h,:]).
//
// Fused single-launch kernel. 1024 blocks x 256 threads; warp w computes row
// blockIdx.x*8+w. Phase 1 FRONT-BATCHES all 8 LDG.128 per thread (MLP=8) —
// launch_bounds(256,4) gives ptxas 64 regs so the loads are not serialized.
// One acq_rel atomic per block on a padded per-batch counter (64 per counter,
// one counter per 128B line). The 64th arriver's warp 0 runs the streaming
// top-6 + softmax + gather. Counters monotonic (64 | 2^32) -> replay safe.

#define B_ 16
#define L_ 512
#define H_ 8
#define HD_ 512
#define K_TOP 6
#define ROWS_PER_BLK 8
#define BLKS_PER_BATCH 64   // 512 / 8
#define CNT_STRIDE 32       // one u32 counter per 128B line

__device__ float g_scores[B_ * L_];
__device__ unsigned int g_cnt[B_ * CNT_STRIDE];  // never reset

// Order-preserving (score,index) pack: bigger score wins, ties -> lower index.
__device__ __forceinline__ unsigned long long packKI(float v, int idx) {
    unsigned int b = __float_as_uint(v);
    b = (b & 0x80000000u) ? ~b : (b | 0x80000000u);
    return ((unsigned long long)b << 32) | (unsigned int)(L_ - 1 - idx);
}
__device__ __forceinline__ float unpackV(unsigned long long p) {
    unsigned int u = (unsigned int)(p >> 32);
    u = (u & 0x80000000u) ? (u ^ 0x80000000u) : ~u;
    return __uint_as_float(u);
}
__device__ __forceinline__ int unpackI(unsigned long long p) {
    return L_ - 1 - (int)(p & 0xFFFFFFFFu);
}
__device__ __forceinline__ unsigned long long u64max(unsigned long long a,
                                                    unsigned long long b) {
    return a > b ? a : b;
}
__device__ __forceinline__ unsigned long long u64min(unsigned long long a,
                                                    unsigned long long b) {
    return a < b ? a : b;
}

// Branch-free insertion of v into descending best[6].
__device__ __forceinline__ void ins6(unsigned long long* best,
                                     unsigned long long v) {
    #pragma unroll
    for (int j = 0; j < K_TOP; j++) {
        unsigned long long lo = u64min(best[j], v);
        best[j] = u64max(best[j], v);
        v = lo;
    }
}

__global__ __launch_bounds__(256, 4) void fused_kernel(
    const float* __restrict__ q, const float* __restrict__ k,
    const float* __restrict__ values, float* __restrict__ out)
{
    const int lane = threadIdx.x & 31;
    const int w    = threadIdx.x >> 5;                 // warp 0..7
    const int bl   = blockIdx.x * ROWS_PER_BLK + w;    // row 0..8191
    const int b    = blockIdx.x >> 6;                  // batch

    // ---- Phase 1: one warp per row, all 8 loads front-batched (MLP=8) ----
    const float4* qp = reinterpret_cast<const float4*>(q) + (size_t)bl * 128;
    const float4* kp = reinterpret_cast<const float4*>(k) + (size_t)bl * 128;

    float4 qv[4], kv[4];
    #pragma unroll
    for (int j = 0; j < 4; j++) qv[j] = __ldg(qp + lane + 32 * j);
    #pragma unroll
    for (int j = 0; j < 4; j++) kv[j] = __ldg(kp + lane + 32 * j);

    float qs[4], ks[4];
    #pragma unroll
    for (int j = 0; j < 4; j++) {
        qs[j] = (qv[j].x + qv[j].y) + (qv[j].z + qv[j].w);
        ks[j] = (kv[j].x + kv[j].y) + (kv[j].z + kv[j].w);
    }
    // Segmented reduce within each 16-lane half (8 head-chains).
    #pragma unroll
    for (int o = 8; o > 0; o >>= 1) {
        #pragma unroll
        for (int j = 0; j < 4; j++) {
            qs[j] += __shfl_down_sync(0xFFFFFFFFu, qs[j], o);
            ks[j] += __shfl_down_sync(0xFFFFFFFFu, ks[j], o);
        }
    }
    // Lane 0 holds heads {0,2,4,6}; lane 16 holds {1,3,5,7}.
    float p = qs[0] * ks[0] + qs[1] * ks[1] + qs[2] * ks[2] + qs[3] * ks[3];
    p += __shfl_down_sync(0xFFFFFFFFu, p, 16);
    if (lane == 0)
        g_scores[bl] = p * (1.0f / (H_ * L_));

    __syncthreads();            // orders all 8 score stores before the RMW
    if (w != 0) return;         // warps 1..7 done

    int win = 0;
    if (lane == 0) {
        unsigned int old;
        asm volatile("atom.acq_rel.gpu.global.add.u32 %0, [%1], %2;"
                     : "=r"(old)
                     : "l"(g_cnt + (size_t)b * CNT_STRIDE), "r"(1u)
                     : "memory");
        win = ((old & (unsigned)(BLKS_PER_BATCH - 1)) ==
               (unsigned)(BLKS_PER_BATCH - 1));
    }
    win = __shfl_sync(0xFFFFFFFFu, win, 0);
    if (!win) return;

    // ---- Phase 2 (winner block's warp 0): top-6 + softmax + gather -------
    // Streaming per-lane top-6 over this lane's 16 scores.
    unsigned long long best[K_TOP] = {0ull, 0ull, 0ull, 0ull, 0ull, 0ull};
    const float4* sp = reinterpret_cast<const float4*>(g_scores + b * L_);
    #pragma unroll
    for (int v4i = 0; v4i < 4; v4i++) {
        float4 s4 = __ldcg(sp + lane * 4 + v4i);
        int base = lane * 16 + v4i * 4;
        ins6(best, packKI(s4.x, base + 0));
        ins6(best, packKI(s4.y, base + 1));
        ins6(best, packKI(s4.z, base + 2));
        ins6(best, packKI(s4.w, base + 3));
    }

    // Merge 32 sorted lists: 6 rounds of warp-max over each lane's head.
    unsigned long long top[K_TOP];
    #pragma unroll
    for (int r = 0; r < K_TOP; r++) {
        unsigned long long m = best[0];
        #pragma unroll
        for (int o = 16; o > 0; o >>= 1)
            m = u64max(m, __shfl_xor_sync(0xFFFFFFFFu, m, o));
        top[r] = m;
        if (best[0] == m) {     // unique owner lane pops its head
            #pragma unroll
            for (int j = 0; j < K_TOP - 1; j++) best[j] = best[j + 1];
            best[K_TOP - 1] = 0ull;
        }
    }

    // Softmax (top[0] is the max) — redundant per lane, no broadcast.
    float m0 = unpackV(top[0]);
    float wgt[K_TOP];
    float s = 0.0f;
    #pragma unroll
    for (int i = 0; i < K_TOP; i++) { wgt[i] = __expf(unpackV(top[i]) - m0); s += wgt[i]; }
    float inv = 1.0f / s;

    // out[b,:] = sum_i w[i] * V[b, idx_i, :]  (128 float4, 4 per lane).
    const float4* vb = reinterpret_cast<const float4*>(values) + (size_t)b * L_ * 128;
    float4 acc[4];
    #pragma unroll
    for (int j = 0; j < 4; j++) acc[j] = make_float4(0.f, 0.f, 0.f, 0.f);

    #pragma unroll
    for (int i = 0; i < K_TOP; i++) {
        float wi = wgt[i] * inv;
        const float4* vp = vb + (size_t)unpackI(top[i]) * 128 + lane;
        #pragma unroll
        for (int j = 0; j < 4; j++) {
            float4 v4 = __ldg(vp + 32 * j);
            acc[j].x = fmaf(wi, v4.x, acc[j].x);
            acc[j].y = fmaf(wi, v4.y, acc[j].y);
            acc[j].z = fmaf(wi, v4.z, acc[j].z);
            acc[j].w = fmaf(wi, v4.w, acc[j].w);
        }
    }
    float4* op = reinterpret_cast<float4*>(out) + (size_t)b * 128 + lane;
    #pragma unroll
    for (int j = 0; j < 4; j++) op[32 * j] = acc[j];
}

extern "C" void kernel_launch(void* const* d_in, const int* in_sizes, int n_in,
                              void* d_out, int out_size)
{
    const float* q = (const float*)d_in[0];
    const float* k = (const float*)d_in[1];
    const float* v = (const float*)d_in[2];
    float* out = (float*)d_out;

    fused_kernel<<<(B_ * L_) / ROWS_PER_BLK, 256>>>(q, k, v, out);
}